// round 16
// baseline (speedup 1.0000x reference)
#include <cuda_runtime.h>
#include <cuda_bf16.h>
#include <stdint.h>
#include <math.h>

#define BB 8
#define NN 2048
#define DIN 512
#define DOUT 256
#define NBUCK 20
#define ROWS (BB*NN)   // 16384

// ---------------- scratch (static __device__, no allocations) ----------------
__device__ __nv_bfloat16 g_qb[ROWS*DOUT];    // q  (bf16)  8 MB
__device__ __nv_bfloat16 g_kb[ROWS*DOUT];    // k  (bf16)  8 MB
__device__ __nv_bfloat16 g_xb[ROWS*DIN];     // x  (bf16) 16 MB
__device__ __nv_bfloat16 g_wqb[DOUT*DIN];    // Wq (bf16)
__device__ __nv_bfloat16 g_wkb[DOUT*DIN];    // Wk (bf16)
__device__ float g_s[ROWS];
__device__ float g_gate3[NBUCK];             // sigmoid(rw*emb) * log2(e) / 16
__device__ float g_wvs[DIN];
__device__ float g_bvs;

// ======================= helpers =======================
__device__ __forceinline__ uint32_t s2u(const void* p) {
    return (uint32_t)__cvta_generic_to_shared(p);
}

// swizzled smem byte offset, 512B rows (32 chunks of 16B)  [128x256 bf16 tile]
__device__ __forceinline__ uint32_t sw(uint32_t row, uint32_t chunk) {
    return row * 512u + ((chunk ^ (row & 7u)) << 4);
}
// swizzled smem byte offset, 256B rows (16 chunks of 16B)  [128x128 bf16 tile]
__device__ __forceinline__ uint32_t sw2(uint32_t row, uint32_t chunk) {
    return row * 256u + ((chunk ^ (row & 7u)) << 4);
}

#define LDSM4(r0,r1,r2,r3,a)                                                     \
    asm volatile("ldmatrix.sync.aligned.m8n8.x4.shared.b16 {%0,%1,%2,%3}, [%4];" \
        : "=r"(r0), "=r"(r1), "=r"(r2), "=r"(r3) : "r"(a))

__device__ __forceinline__ void mma16816(float* c, uint32_t a0, uint32_t a1,
                                         uint32_t a2, uint32_t a3,
                                         uint32_t b0, uint32_t b1) {
    asm volatile("mma.sync.aligned.m16n8k16.row.col.f32.bf16.bf16.f32 "
        "{%0,%1,%2,%3}, {%4,%5,%6,%7}, {%8,%9}, {%0,%1,%2,%3};"
        : "+f"(c[0]), "+f"(c[1]), "+f"(c[2]), "+f"(c[3])
        : "r"(a0), "r"(a1), "r"(a2), "r"(a3), "r"(b0), "r"(b1));
}

#define CP16(dst, src) asm volatile("cp.async.cg.shared.global [%0], [%1], 16;" :: "r"(dst), "l"(src) : "memory")
#define CP_COMMIT()    asm volatile("cp.async.commit_group;" ::: "memory")
#define CP_WAIT0()     asm volatile("cp.async.wait_group 0;" ::: "memory")
#define CP_WAIT1()     asm volatile("cp.async.wait_group 1;" ::: "memory")
#define CP_WAIT2()     asm volatile("cp.async.wait_group 2;" ::: "memory")

// ---------------- packed f32x2 helpers (sm_100+ baseline ISA) ----------------
__device__ __forceinline__ uint64_t pk2(float lo, float hi) {
    uint64_t r; asm("mov.b64 %0, {%1, %2};" : "=l"(r) : "f"(lo), "f"(hi)); return r;
}
__device__ __forceinline__ float2 upk2(uint64_t v) {
    float2 r; asm("mov.b64 {%0, %1}, %2;" : "=f"(r.x), "=f"(r.y) : "l"(v)); return r;
}
#define F2ADD(d,a,b)     asm("add.rn.f32x2 %0, %1, %2;" : "=l"(d) : "l"(a), "l"(b))
#define F2MUL(d,a,b)     asm("mul.rn.f32x2 %0, %1, %2;" : "=l"(d) : "l"(a), "l"(b))
#define F2FMA(d,a,b,c)   asm("fma.rn.f32x2 %0, %1, %2, %3;" : "=l"(d) : "l"(a), "l"(b), "l"(c))
#define F2ACC(acc,e)     asm("add.rn.f32x2 %0, %0, %1;" : "+l"(acc) : "l"(e))
#define F2FMAACC(acc,a,b) asm("fma.rn.f32x2 %0, %1, %2, %0;" : "+l"(acc) : "l"(a), "l"(b))

// packed 2^y for a column-pair, deg-4, magic-number exponent extraction
__device__ __forceinline__ uint64_t exp2x2(uint64_t y) {
    const uint64_t BIG  = pk2(12582912.0f, 12582912.0f);
    const uint64_t NBIG = pk2(-12582912.0f, -12582912.0f);
    const uint64_t NONE = pk2(-1.0f, -1.0f);
    const uint64_t C3   = pk2(9.6181291e-3f, 9.6181291e-3f);
    const uint64_t C2   = pk2(5.5504109e-2f, 5.5504109e-2f);
    const uint64_t C1   = pk2(2.4022652e-1f, 2.4022652e-1f);
    const uint64_t C0   = pk2(6.9314718e-1f, 6.9314718e-1f);
    const uint64_t ONE  = pk2(1.0f, 1.0f);
    uint64_t z, w, f, p1, p2, p3, p4;
    F2ADD(z, y, BIG);          // round(y) encoded in mantissa
    F2ADD(w, z, NBIG);         // w = round(y)
    F2FMA(f, w, NONE, y);      // f = y - w, in [-0.5, 0.5]
    F2FMA(p1, C3, f, C2);
    F2FMA(p2, p1, f, C1);
    F2FMA(p3, p2, f, C0);
    F2FMA(p4, p3, f, ONE);
    uint32_t zl, zh;
    asm("mov.b64 {%0, %1}, %2;" : "=r"(zl), "=r"(zh) : "l"(z));
    float2 pf = upk2(p4);
    float e0 = pf.x * __uint_as_float((zl << 23) + 0x3f800000u);
    float e1 = pf.y * __uint_as_float((zh << 23) + 0x3f800000u);
    return pk2(e0, e1);
}

// ======================= prep: wvs GEMV + gate LUT + bvs (one launch) =======================
__global__ void prep_all(const float* __restrict__ Wv, const float* __restrict__ bv,
                         const float* __restrict__ Ws, const float* __restrict__ remb,
                         const float* __restrict__ rw) {
    int blk = blockIdx.x, t = threadIdx.x;
    if (blk < 8) {
        int d = blk * 64 + t;
        float acc = 0.f;
        #pragma unroll 8
        for (int o = 0; o < DOUT; o++) acc += Wv[(size_t)o * DIN + d] * __ldg(Ws + o);
        g_wvs[d] = acc;
    } else {
        if (t < NBUCK) {
            float zv = rw[0] * remb[t];
            float sg = 1.f / (1.f + expf(-zv));
            g_gate3[t] = sg * (1.44269504088896f / 16.0f);  // fold log2e / sqrt(DOUT)
        }
        if (t >= 32 && t < 64) {
            int l = t - 32;
            float acc = 0.f;
            #pragma unroll
            for (int o = l; o < DOUT; o += 32) acc += bv[o] * Ws[o];
            #pragma unroll
            for (int s = 16; s; s >>= 1) acc += __shfl_xor_sync(0xffffffffu, acc, s);
            if (l == 0) g_bvs = acc;
        }
    }
}

// ======================= fused x convert + s + weight convert =======================
// blocks [0, ROWS/8): one warp per x row (convert + dot with wvs)
// blocks [ROWS/8, ROWS/8+128): Wq/Wk fp32 -> bf16
#define W4 (DOUT*DIN/4)
__global__ void xs_kernel(const float* __restrict__ x, const float* __restrict__ Wq,
                          const float* __restrict__ Wk) {
    if (blockIdx.x < ROWS / 8) {
        int row  = blockIdx.x * 8 + (threadIdx.x >> 5);
        int lane = threadIdx.x & 31;
        const float4* xr = (const float4*)(x + (size_t)row * DIN);
        const float4* wv = (const float4*)g_wvs;
        uint2* xb = (uint2*)(g_xb + (size_t)row * DIN);
        float acc = 0.f;
        #pragma unroll
        for (int i = 0; i < 4; i++) {
            int idx = lane + i * 32;
            float4 a = xr[idx];
            float4 b = wv[idx];
            acc += a.x*b.x + a.y*b.y + a.z*b.z + a.w*b.w;
            __nv_bfloat162 h0 = __floats2bfloat162_rn(a.x, a.y);
            __nv_bfloat162 h1 = __floats2bfloat162_rn(a.z, a.w);
            uint2 u; u.x = *(uint32_t*)&h0; u.y = *(uint32_t*)&h1;
            xb[idx] = u;
        }
        #pragma unroll
        for (int s = 16; s; s >>= 1) acc += __shfl_xor_sync(0xffffffffu, acc, s);
        if (lane == 0) g_s[row] = acc + g_bvs;
    } else {
        int base = (blockIdx.x - ROWS / 8) * 256 + threadIdx.x;   // 0..32767
        #pragma unroll
        for (int rep = 0; rep < 2; rep++) {
            int i = base + rep * 32768;                           // 0..65535
            const float* src = (i < W4) ? Wq : Wk;
            __nv_bfloat16* dst = (i < W4) ? g_wqb : g_wkb;
            int j = (i < W4) ? i : i - W4;
            float4 v = *(const float4*)(src + (size_t)j * 4);
            __nv_bfloat162 h0 = __floats2bfloat162_rn(v.x, v.y);
            __nv_bfloat162 h1 = __floats2bfloat162_rn(v.z, v.w);
            uint2 u; u.x = *(uint32_t*)&h0; u.y = *(uint32_t*)&h1;
            *(uint2*)(dst + (size_t)j * 4) = u;
        }
    }
}

// ======================= QK projection: persistent-A, 3-deep B pipeline =======================
// Grid 128 CTAs. A = x[128,512] resident (4 x 32KB), B streamed through 3 x 32KB ring.
#define QKP_SMEM (131072 + 98304 + 1024)

__global__ __launch_bounds__(512, 1) void qk_mma(const float* __restrict__ bq,
                                                 const float* __restrict__ bk) {
    extern __shared__ char dsm[];
    uint32_t base0 = s2u(dsm);
    uint32_t A0 = (base0 + 1023u) & ~1023u;

    const int t = threadIdx.x, w = t >> 5, lane = t & 31;
    const int wr = w >> 2, wc = w & 3;
    const int row0 = blockIdx.x * 128;

    const uint32_t SB[3] = { A0 + 131072, A0 + 163840, A0 + 196608 };
    const __nv_bfloat16* asrc = g_xb + (size_t)row0 * DIN;

    const int r0 = wr * 32;
    const uint32_t arow = (uint32_t)(r0 + ((lane >> 3) & 1) * 8 + (lane & 7));
    const uint32_t ac   = (uint32_t)((lane >> 4) & 1);
    const uint32_t brlo = (uint32_t)(wc * 32 + ((lane >> 4) & 1) * 8 + (lane & 7));
    const uint32_t bc   = (uint32_t)((lane >> 3) & 1);

    // prefetch all 4 A chunks (one commit group each)
    #pragma unroll
    for (int h = 0; h < 4; h++) {
        #pragma unroll
        for (int it = 0; it < 4; it++) {
            int idx = t + it * 512;
            int r = idx >> 4, c = idx & 15;
            CP16(A0 + h * 32768 + sw2(r, c), asrc + (size_t)r * DIN + h * 128 + c * 8);
        }
        CP_COMMIT();
    }
    // prefetch B tiles for iterations 0..2
    #pragma unroll
    for (int j = 0; j < 3; j++) {
        const int yn = j >> 2, hn = j & 3;
        const __nv_bfloat16* bsrc = ((yn < 2) ? g_wqb : g_wkb)
                                    + (size_t)((yn & 1) * 128) * DIN + hn * 128;
        #pragma unroll
        for (int it = 0; it < 4; it++) {
            int idx = t + it * 512;
            int r = idx >> 4, c = idx & 15;
            CP16(SB[j] + sw2(r, c), bsrc + (size_t)r * DIN + c * 8);
        }
        CP_COMMIT();
    }

    float acc[8][4];

    for (int i = 0; i < 16; i++) {
        const int yc = i >> 2, h = i & 3;
        const uint32_t SBb = SB[i % 3];
        if (i < 14) { CP_WAIT2(); } else if (i == 14) { CP_WAIT1(); } else { CP_WAIT0(); }
        __syncthreads();

        if (h == 0) {
            #pragma unroll
            for (int j = 0; j < 8; j++) { acc[j][0]=0.f; acc[j][1]=0.f; acc[j][2]=0.f; acc[j][3]=0.f; }
        }

        const uint32_t SAh = A0 + h * 32768;
        #pragma unroll
        for (int ks = 0; ks < 8; ks++) {
            uint32_t a0,a1,a2,a3,a4,a5,a6,a7;
            LDSM4(a0,a1,a2,a3, SAh + sw2(arow,      (uint32_t)(ks*2) + ac));
            LDSM4(a4,a5,a6,a7, SAh + sw2(arow + 16, (uint32_t)(ks*2) + ac));
            uint32_t b0,b1,b2,b3,b4,b5,b6,b7;
            LDSM4(b0,b1,b2,b3, SBb + sw2(brlo,      (uint32_t)(ks*2) + bc));
            LDSM4(b4,b5,b6,b7, SBb + sw2(brlo + 16, (uint32_t)(ks*2) + bc));
            mma16816(acc[0], a0,a1,a2,a3, b0,b1);
            mma16816(acc[1], a0,a1,a2,a3, b2,b3);
            mma16816(acc[2], a0,a1,a2,a3, b4,b5);
            mma16816(acc[3], a0,a1,a2,a3, b6,b7);
            mma16816(acc[4], a4,a5,a6,a7, b0,b1);
            mma16816(acc[5], a4,a5,a6,a7, b2,b3);
            mma16816(acc[6], a4,a5,a6,a7, b4,b5);
            mma16816(acc[7], a4,a5,a6,a7, b6,b7);
        }

        if (h == 3) {
            // epilogue for this yc: bias add, bf16 store
            const float* bias   = (yc < 2) ? bq : bk;
            __nv_bfloat16* outp = (yc < 2) ? g_qb : g_kb;
            const int col0 = (yc & 1) * 128;
            #pragma unroll
            for (int rb = 0; rb < 2; rb++) {
                #pragma unroll
                for (int nb = 0; nb < 4; nb++) {
                    const float* a4 = acc[rb * 4 + nb];
                    int col = col0 + wc * 32 + nb * 8 + (lane & 3) * 2;
                    float b0 = __ldg(bias + col), b1 = __ldg(bias + col + 1);
                    int ra = row0 + r0 + rb * 16 + (lane >> 2);
                    __nv_bfloat162 lo = __floats2bfloat162_rn(a4[0] + b0, a4[1] + b1);
                    __nv_bfloat162 hi = __floats2bfloat162_rn(a4[2] + b0, a4[3] + b1);
                    *(uint32_t*)(outp + (size_t)ra * DOUT + col)       = *(uint32_t*)&lo;
                    *(uint32_t*)(outp + (size_t)(ra + 8) * DOUT + col) = *(uint32_t*)&hi;
                }
            }
        }
        __syncthreads();   // all warps done with SB[i%3] before prefetch overwrites it

        if (i + 3 < 16) {
            const int j = i + 3, yn = j >> 2, hn = j & 3;
            const __nv_bfloat16* bsrc = ((yn < 2) ? g_wqb : g_wkb)
                                        + (size_t)((yn & 1) * 128) * DIN + hn * 128;
            const uint32_t dstB = SB[i % 3];
            #pragma unroll
            for (int it = 0; it < 4; it++) {
                int idx = t + it * 512;
                int r = idx >> 4, c = idx & 15;
                CP16(dstB + sw2(r, c), bsrc + (size_t)r * DIN + c * 8);
            }
            CP_COMMIT();
        }
    }
}

// ======================= fused attention: mma.sync scores + packed f32x2 epilogue =======================
// smem: Q 64KB | K0 64KB | K1 64KB | kvall 16KB | g3 2560B | red 4096B
#define AT_Q   0
#define AT_K0  65536
#define AT_K1  131072
#define AT_KV  196608
#define AT_G3  212992
#define AT_RED 215552
#define ATTN_SMEM (219648 + 1024)

__global__ __launch_bounds__(512, 1) void attn_mma(const long long* __restrict__ pr,
                                                   const float* __restrict__ bs_p,
                                                   float* __restrict__ out) {
    extern __shared__ char dsm[];
    uint32_t base0 = s2u(dsm);
    uint32_t A0 = (base0 + 1023u) & ~1023u;
    char* P = dsm + (A0 - base0);

    const int t = threadIdx.x, w = t >> 5, lane = t & 31;
    const int wr = w >> 2, wc = w & 3;
    const int b = blockIdx.y, n0 = blockIdx.x * 128;

    const uint32_t SQ = A0 + AT_Q;
    const uint32_t SK[2] = { A0 + AT_K0, A0 + AT_K1 };
    float2* kvall = (float2*)(P + AT_KV);
    float*  g3    = (float*)(P + AT_G3);
    float*  redl  = (float*)(P + AT_RED);        // [4][128]
    float*  reda  = (float*)(P + AT_RED + 2048); // [4][128]

    // initial async loads: Q tile + K tile 0
    const __nv_bfloat16* qsrc = g_qb + ((size_t)b * NN + n0) * DOUT;
    const __nv_bfloat16* ksrc = g_kb + (size_t)b * NN * DOUT;
    #pragma unroll
    for (int it = 0; it < 8; it++) {
        int idx = t + it * 512;
        int r = idx >> 5, c = idx & 31;
        CP16(SQ + sw(r, c), qsrc + (size_t)r * DOUT + c * 8);
        CP16(SK[0] + sw(r, c), ksrc + (size_t)r * DOUT + c * 8);
    }
    CP_COMMIT();

    // kvall + gate LUT
    #pragma unroll
    for (int it = 0; it < 4; it++) {
        int idx = t + it * 512;
        kvall[idx] = make_float2(g_s[(size_t)b * NN + idx],
                                 __int_as_float((int)pr[(size_t)b * NN + idx]));
    }
    for (int i = t; i < NBUCK * 32; i += 512) g3[i] = g_gate3[i >> 5];

    const int r0 = wr * 32;
    unsigned rn[4];
    #pragma unroll
    for (int i = 0; i < 4; i++)
        rn[i] = (unsigned)(int)pr[(size_t)b * NN + n0 + r0 + (lane >> 2) + i * 8];

    const uint32_t arow = (uint32_t)(r0 + ((lane >> 3) & 1) * 8 + (lane & 7));
    const uint32_t ac   = (uint32_t)((lane >> 4) & 1);
    const uint32_t brlo = (uint32_t)(wc * 32 + ((lane >> 4) & 1) * 8 + (lane & 7));
    const uint32_t bc   = (uint32_t)((lane >> 3) & 1);

    uint64_t lacp[4], aacp[4];
    #pragma unroll
    for (int i = 0; i < 4; i++) { lacp[i] = pk2(0.f, 0.f); aacp[i] = pk2(0.f, 0.f); }

    CP_WAIT0();
    __syncthreads();

    for (int tile = 0; tile < 16; tile++) {
        const int buf = tile & 1;
        if (tile + 1 < 16) {
            const __nv_bfloat16* kn = ksrc + (size_t)(tile + 1) * 128 * DOUT;
            #pragma unroll
            for (int it = 0; it < 8; it++) {
                int idx = t + it * 512;
                int r = idx >> 5, c = idx & 31;
                CP16(SK[1 - buf] + sw(r, c), kn + (size_t)r * DOUT + c * 8);
            }
            CP_COMMIT();
        }

        // ---- scores mma: warp covers rows r0..r0+31, cols wc*32..+31 ----
        float acc[8][4];
        #pragma unroll
        for (int j = 0; j < 8; j++) { acc[j][0]=0.f; acc[j][1]=0.f; acc[j][2]=0.f; acc[j][3]=0.f; }

        const uint32_t SKb = SK[buf];
        #pragma unroll
        for (int ks = 0; ks < 16; ks++) {
            uint32_t a0,a1,a2,a3,a4,a5,a6,a7;
            LDSM4(a0,a1,a2,a3, SQ + sw(arow,      (uint32_t)(ks*2) + ac));
            LDSM4(a4,a5,a6,a7, SQ + sw(arow + 16, (uint32_t)(ks*2) + ac));
            uint32_t b0,b1,b2,b3,b4,b5,b6,b7;
            LDSM4(b0,b1,b2,b3, SKb + sw(brlo,      (uint32_t)(ks*2) + bc));
            LDSM4(b4,b5,b6,b7, SKb + sw(brlo + 16, (uint32_t)(ks*2) + bc));
            mma16816(acc[0], a0,a1,a2,a3, b0,b1);
            mma16816(acc[1], a0,a1,a2,a3, b2,b3);
            mma16816(acc[2], a0,a1,a2,a3, b4,b5);
            mma16816(acc[3], a0,a1,a2,a3, b6,b7);
            mma16816(acc[4], a4,a5,a6,a7, b0,b1);
            mma16816(acc[5], a4,a5,a6,a7, b2,b3);
            mma16816(acc[6], a4,a5,a6,a7, b4,b5);
            mma16816(acc[7], a4,a5,a6,a7, b6,b7);
        }

        // ---- epilogue: packed f32x2 gate + exp + accumulate ----
        const float2* kva = kvall + tile * 128;
        #pragma unroll
        for (int nb = 0; nb < 4; nb++) {
            int col = wc * 32 + nb * 8 + (lane & 3) * 2;
            float2 kv0 = kva[col];
            float2 kv1 = kva[col + 1];
            unsigned rm0 = (unsigned)__float_as_int(kv0.y);
            unsigned rm1 = (unsigned)__float_as_int(kv1.y);
            uint64_t kvx = pk2(kv0.x, kv1.x);
            #pragma unroll
            for (int rb = 0; rb < 2; rb++) {
                const float* a4 = acc[rb * 4 + nb];
                unsigned rA = rn[rb * 2], rB = rn[rb * 2 + 1];
                unsigned k00 = umin(__usad(rA, rm0, 0u) / 5u, NBUCK - 1u);
                unsigned k01 = umin(__usad(rA, rm1, 0u) / 5u, NBUCK - 1u);
                unsigned k10 = umin(__usad(rB, rm0, 0u) / 5u, NBUCK - 1u);
                unsigned k11 = umin(__usad(rB, rm1, 0u) / 5u, NBUCK - 1u);
                uint64_t yA;
                F2MUL(yA, pk2(a4[0], a4[1]), pk2(g3[k00 * 32 + lane], g3[k01 * 32 + lane]));
                uint64_t eA = exp2x2(yA);
                F2ACC(lacp[rb * 2], eA);
                F2FMAACC(aacp[rb * 2], eA, kvx);
                uint64_t yB;
                F2MUL(yB, pk2(a4[2], a4[3]), pk2(g3[k10 * 32 + lane], g3[k11 * 32 + lane]));
                uint64_t eB = exp2x2(yB);
                F2ACC(lacp[rb * 2 + 1], eB);
                F2FMAACC(aacp[rb * 2 + 1], eB, kvx);
            }
        }

        CP_WAIT0();
        __syncthreads();
    }

    // collapse packed halves, then intra-warp reduce over the 4 lanes per row
    float lac[4], aac[4];
    #pragma unroll
    for (int i = 0; i < 4; i++) {
        float2 lv = upk2(lacp[i]); lac[i] = lv.x + lv.y;
        float2 av = upk2(aacp[i]); aac[i] = av.x + av.y;
    }
    #pragma unroll
    for (int s = 1; s <= 2; s <<= 1) {
        #pragma unroll
        for (int i = 0; i < 4; i++) {
            lac[i] += __shfl_xor_sync(0xffffffffu, lac[i], s);
            aac[i] += __shfl_xor_sync(0xffffffffu, aac[i], s);
        }
    }
    if ((lane & 3) == 0) {
        #pragma unroll
        for (int i = 0; i < 4; i++) {
            int row = r0 + (lane >> 2) + i * 8;
            redl[wc * 128 + row] = lac[i];
            reda[wc * 128 + row] = aac[i];
        }
    }
    __syncthreads();
    if (t < 128) {
        float L = redl[t] + redl[128 + t] + redl[256 + t] + redl[384 + t];
        float A = reda[t] + reda[128 + t] + reda[256 + t] + reda[384 + t];
        float z = A / L + bs_p[0];
        out[(size_t)b * NN + t + n0] = 1.f / (1.f + expf(-z));
    }
}

// ======================= launcher =======================
extern "C" void kernel_launch(void* const* d_in, const int* in_sizes, int n_in,
                              void* d_out, int out_size) {
    const float*     x    = (const float*)d_in[0];
    const long long* pr   = (const long long*)d_in[1];
    const float*     Wq   = (const float*)d_in[2];
    const float*     bq   = (const float*)d_in[3];
    const float*     Wk   = (const float*)d_in[4];
    const float*     bk   = (const float*)d_in[5];
    const float*     Wv   = (const float*)d_in[6];
    const float*     bv   = (const float*)d_in[7];
    const float*     Ws   = (const float*)d_in[8];
    const float*     bs   = (const float*)d_in[9];
    const float*     remb = (const float*)d_in[10];
    const float*     rw   = (const float*)d_in[11];
    float* out = (float*)d_out;

    prep_all<<<9, 64>>>(Wv, bv, Ws, remb, rw);           // wvs + gate + bvs
    xs_kernel<<<ROWS/8 + 128, 256>>>(x, Wq, Wk);         // x->bf16 + s, W->bf16

    cudaFuncSetAttribute(qk_mma, cudaFuncAttributeMaxDynamicSharedMemorySize, QKP_SMEM);
    qk_mma<<<ROWS/128, 512, QKP_SMEM>>>(bq, bk);

    cudaFuncSetAttribute(attn_mma, cudaFuncAttributeMaxDynamicSharedMemorySize, ATTN_SMEM);
    dim3 g2(NN/128, BB);
    attn_mma<<<g2, 512, ATTN_SMEM>>>(pr, bs, out);
}